// round 2
// baseline (speedup 1.0000x reference)
#include <cuda_runtime.h>

#define N_NODES 100000
#define N_EDGES 1250000
#define D 64

// ---------------- scratch (static __device__ — allocation-free) ----------------
__device__ int   g_is64;
__device__ int   g_cnt[N_NODES];
__device__ int   g_rowoff[N_NODES + 1];
__device__ int   g_cursor[N_NODES];
__device__ int   g_sorted_src[N_EDGES];
__device__ float g_xlin[N_NODES * D];
__device__ float g_asrc[N_NODES * D];
__device__ float g_adst[N_NODES * D];

// ---------------- dtype detection for edge_index ----------------
// If the buffer really holds int64 node indices, every value is in [0, N).
// If it holds int32, reading as int64 fuses two indices: lo + hi*2^32, which
// exceeds N unless hi==0 (prob 1e-5 per entry). 16 entries => certain.
__global__ void k_detect(const void* __restrict__ eiv) {
    const long long* p = (const long long*)eiv;
    int is64 = 1;
    for (int i = 0; i < 16; i++) {
        long long v = p[i];
        if (v < 0 || v >= (long long)N_NODES) is64 = 0;
    }
    g_is64 = is64;
}

__device__ __forceinline__ int load_idx(const void* eiv, int pos64) {
    if (g_is64) return (int)((const long long*)eiv)[pos64];
    return ((const int*)eiv)[pos64];
}

// ---------------- counting sort of edges by dst ----------------
__global__ void k_zero_cnt() {
    int i = blockIdx.x * blockDim.x + threadIdx.x;
    if (i < N_NODES) g_cnt[i] = 0;
}

__global__ void k_hist(const void* __restrict__ eiv) {
    int e = blockIdx.x * blockDim.x + threadIdx.x;
    if (e < N_EDGES) {
        int d = load_idx(eiv, N_EDGES + e);   // dst = edge_index[1]
        if ((unsigned)d < (unsigned)N_NODES) atomicAdd(&g_cnt[d], 1);
    }
}

__global__ void k_scan() {
    __shared__ int ss[1024];
    int t = threadIdx.x;
    const int per = (N_NODES + 1023) / 1024;  // 98
    int beg = t * per;
    int end = min(beg + per, N_NODES);
    int s = 0;
    for (int i = beg; i < end; i++) s += g_cnt[i];
    ss[t] = s;
    __syncthreads();
    // inclusive Hillis-Steele scan over 1024 partials
    for (int off = 1; off < 1024; off <<= 1) {
        int v = ss[t];
        int add = (t >= off) ? ss[t - off] : 0;
        __syncthreads();
        ss[t] = v + add;
        __syncthreads();
    }
    int run = (t == 0) ? 0 : ss[t - 1];
    for (int i = beg; i < end; i++) {
        g_rowoff[i] = run;
        g_cursor[i] = run;
        run += g_cnt[i];
    }
    if (t == 1023) g_rowoff[N_NODES] = run;
}

__global__ void k_scatter(const void* __restrict__ eiv) {
    int e = blockIdx.x * blockDim.x + threadIdx.x;
    if (e < N_EDGES) {
        int d = load_idx(eiv, N_EDGES + e);
        int s = load_idx(eiv, e);
        if ((unsigned)d < (unsigned)N_NODES) {
            int p = atomicAdd(&g_cursor[d], 1);
            g_sorted_src[p] = ((unsigned)s < (unsigned)N_NODES) ? s : 0;
        }
    }
}

// ---------------- node projections: h = relu(xW_in+b); xlin/asrc/adst = h@W ----------------
// 4 nodes per block (blockDim=64, one channel per thread) to amortize weight LDGs.
__global__ void k_nodeproj(const float* __restrict__ x,
                           const float* __restrict__ W_in, const float* __restrict__ b_in,
                           const float* __restrict__ W_lin, const float* __restrict__ W_src,
                           const float* __restrict__ W_dst) {
    __shared__ float sh[4][D];
    int c = threadIdx.x;
    int n0 = blockIdx.x * 4;

#pragma unroll
    for (int r = 0; r < 4; r++) sh[r][c] = x[(n0 + r) * D + c];
    __syncthreads();

    float h[4];
    float bi = b_in[c];
#pragma unroll
    for (int r = 0; r < 4; r++) h[r] = bi;
#pragma unroll
    for (int k = 0; k < D; k++) {
        float w = W_in[k * D + c];
#pragma unroll
        for (int r = 0; r < 4; r++) h[r] = fmaf(sh[r][k], w, h[r]);
    }
    __syncthreads();
#pragma unroll
    for (int r = 0; r < 4; r++) sh[r][c] = fmaxf(h[r], 0.0f);
    __syncthreads();

    float v1[4] = {0.f, 0.f, 0.f, 0.f};
    float v2[4] = {0.f, 0.f, 0.f, 0.f};
    float v3[4] = {0.f, 0.f, 0.f, 0.f};
#pragma unroll
    for (int k = 0; k < D; k++) {
        float w1 = W_lin[k * D + c];
        float w2 = W_src[k * D + c];
        float w3 = W_dst[k * D + c];
#pragma unroll
        for (int r = 0; r < 4; r++) {
            float hk = sh[r][k];
            v1[r] = fmaf(hk, w1, v1[r]);
            v2[r] = fmaf(hk, w2, v2[r]);
            v3[r] = fmaf(hk, w3, v3[r]);
        }
    }
#pragma unroll
    for (int r = 0; r < 4; r++) {
        g_xlin[(n0 + r) * D + c] = v1[r];
        g_asrc[(n0 + r) * D + c] = v2[r];
        g_adst[(n0 + r) * D + c] = v3[r];
    }
}

// ---------------- fused edge pass: online segment-softmax + aggregate + out-proj ----------------
// one block (64 threads = 2 warps) per destination node; thread = channel.
__global__ void k_edge(const float* __restrict__ pos,
                       const float* __restrict__ W_pos, const float* __restrict__ b_pos,
                       const float* __restrict__ W_out, const float* __restrict__ b_out,
                       float* __restrict__ out) {
    __shared__ float sh[D];
    int dst = blockIdx.x;
    int c = threadIdx.x;

    int rs = g_rowoff[dst];
    int re = g_rowoff[dst + 1];

    float ad  = g_adst[dst * D + c];
    float pd0 = pos[dst * 3 + 0];
    float pd1 = pos[dst * 3 + 1];
    float pd2 = pos[dst * 3 + 2];
    float wp0 = W_pos[0 * D + c];
    float wp1 = W_pos[1 * D + c];
    float wp2 = W_pos[2 * D + c];
    float bp  = b_pos[c];

    float m = -1e30f;
    float s = 0.0f;
    float acc = 0.0f;

    for (int e = rs; e < re; e++) {
        int src = g_sorted_src[e];
        float as = g_asrc[src * D + c];
        float xl = g_xlin[src * D + c];
        float d0 = pd0 - pos[src * 3 + 0];
        float d1 = pd1 - pos[src * 3 + 1];
        float d2 = pd2 - pos[src * 3 + 2];
        float delta = fmaf(d2, wp2, fmaf(d1, wp1, fmaf(d0, wp0, bp)));
        float a = ad - as + delta;
        float v = xl + delta;
        float nm = fmaxf(m, a);
        float sc = __expf(m - nm);
        float p  = __expf(a - nm);
        s   = fmaf(s, sc, p);
        acc = fmaf(acc, sc, p * v);
        m = nm;
    }

    float r = acc / (s + 1e-16f);
    sh[c] = r;
    __syncthreads();

    float o = b_out[c];
#pragma unroll
    for (int k = 0; k < D; k++) o = fmaf(sh[k], W_out[k * D + c], o);
    out[dst * D + c] = fmaxf(o, 0.0f);
}

// ---------------- launch ----------------
extern "C" void kernel_launch(void* const* d_in, const int* in_sizes, int n_in,
                              void* d_out, int out_size) {
    const float* x     = (const float*)d_in[0];
    const float* pos   = (const float*)d_in[1];
    const void*  ei    = d_in[2];
    const float* W_in  = (const float*)d_in[3];
    const float* b_in  = (const float*)d_in[4];
    const float* W_lin = (const float*)d_in[5];
    const float* W_src = (const float*)d_in[6];
    const float* W_dst = (const float*)d_in[7];
    const float* W_pos = (const float*)d_in[8];
    const float* b_pos = (const float*)d_in[9];
    const float* W_out = (const float*)d_in[10];
    const float* b_out = (const float*)d_in[11];
    float* out = (float*)d_out;

    k_detect<<<1, 1>>>(ei);
    k_zero_cnt<<<(N_NODES + 255) / 256, 256>>>();
    k_hist<<<(N_EDGES + 255) / 256, 256>>>(ei);
    k_scan<<<1, 1024>>>();
    k_scatter<<<(N_EDGES + 255) / 256, 256>>>(ei);
    k_nodeproj<<<N_NODES / 4, 64>>>(x, W_in, b_in, W_lin, W_src, W_dst);
    k_edge<<<N_NODES, 64>>>(pos, W_pos, b_pos, W_out, b_out, out);
}

// round 3
// speedup vs baseline: 1.8443x; 1.8443x over previous
#include <cuda_runtime.h>

#define N_NODES 100000
#define N_EDGES 1250000
#define D 64
#define NB 98          // scan blocks: ceil(N/1024)

// ---------------- scratch (static __device__ — allocation-free) ----------------
__device__ int    g_is64;
__device__ int    g_cnt[N_NODES];
__device__ int    g_iscan[N_NODES];
__device__ int    g_rowoff[N_NODES + 1];
__device__ int    g_cursor[N_NODES];
__device__ int    g_bsum[NB];
__device__ int    g_boff[NB];
__device__ int    g_sorted_src[N_EDGES];
__device__ float2 g_pack[N_NODES * D];   // (a_src, x_lin) interleaved for the edge gather
__device__ float  g_adst[N_NODES * D];
__device__ float  g_agg[N_NODES * D];    // softmax-aggregated messages (pre out-proj)

// ---------------- f32x2 packed helpers ----------------
__device__ __forceinline__ unsigned long long pack2(float lo, float hi) {
    unsigned long long r;
    asm("mov.b64 %0, {%1, %2};" : "=l"(r) : "f"(lo), "f"(hi));
    return r;
}
__device__ __forceinline__ void unpack2(unsigned long long v, float& lo, float& hi) {
    asm("mov.b64 {%0, %1}, %2;" : "=f"(lo), "=f"(hi) : "l"(v));
}
__device__ __forceinline__ unsigned long long fma2(unsigned long long a,
                                                   unsigned long long b,
                                                   unsigned long long c) {
    unsigned long long d;
    asm("fma.rn.f32x2 %0, %1, %2, %3;" : "=l"(d) : "l"(a), "l"(b), "l"(c));
    return d;
}

// ---------------- dtype detection for edge_index ----------------
__global__ void k_detect(const void* __restrict__ eiv) {
    const long long* p = (const long long*)eiv;
    int is64 = 1;
    for (int i = 0; i < 16; i++) {
        long long v = p[i];
        if (v < 0 || v >= (long long)N_NODES) is64 = 0;
    }
    g_is64 = is64;
}

__device__ __forceinline__ int load_idx(const void* eiv, int pos64) {
    if (g_is64) return (int)((const long long*)eiv)[pos64];
    return ((const int*)eiv)[pos64];
}

// ---------------- counting sort of edges by dst ----------------
__global__ void k_zero_cnt() {
    int i = blockIdx.x * blockDim.x + threadIdx.x;
    if (i < N_NODES) g_cnt[i] = 0;
}

__global__ void k_hist(const void* __restrict__ eiv) {
    int e = blockIdx.x * blockDim.x + threadIdx.x;
    if (e < N_EDGES) {
        int d = load_idx(eiv, N_EDGES + e);
        if ((unsigned)d < (unsigned)N_NODES) atomicAdd(&g_cnt[d], 1);
    }
}

// 98 blocks x 1024: per-block inclusive scan (shuffle), block totals to g_bsum
__global__ void k_blockscan() {
    __shared__ int warpsum[32];
    int t = threadIdx.x;
    int i = blockIdx.x * 1024 + t;
    int v = (i < N_NODES) ? g_cnt[i] : 0;
    int x = v;
#pragma unroll
    for (int o = 1; o < 32; o <<= 1) {
        int y = __shfl_up_sync(0xffffffffu, x, o);
        if ((t & 31) >= o) x += y;
    }
    if ((t & 31) == 31) warpsum[t >> 5] = x;
    __syncthreads();
    if (t < 32) {
        int w = warpsum[t];
#pragma unroll
        for (int o = 1; o < 32; o <<= 1) {
            int y = __shfl_up_sync(0xffffffffu, w, o);
            if (t >= o) w += y;
        }
        warpsum[t] = w;
    }
    __syncthreads();
    int wid = t >> 5;
    int incl = x + (wid ? warpsum[wid - 1] : 0);
    if (i < N_NODES) g_iscan[i] = incl;
    if (t == 1023) g_bsum[blockIdx.x] = incl;
}

// 1 block x 32: exclusive scan of the 98 block sums; also writes rowoff[N]
__global__ void k_bsum_scan() {
    int t = threadIdx.x;
    int loc[4];
    int s = 0;
#pragma unroll
    for (int j = 0; j < 4; j++) {
        int i = t * 4 + j;
        int v = (i < NB) ? g_bsum[i] : 0;
        loc[j] = s;
        s += v;
    }
    int x = s;
#pragma unroll
    for (int o = 1; o < 32; o <<= 1) {
        int y = __shfl_up_sync(0xffffffffu, x, o);
        if (t >= o) x += y;
    }
    int excl = x - s;
#pragma unroll
    for (int j = 0; j < 4; j++) {
        int i = t * 4 + j;
        if (i < NB) g_boff[i] = excl + loc[j];
    }
    if (t == 31) g_rowoff[N_NODES] = x;
}

__global__ void k_finalize() {
    int i = blockIdx.x * 1024 + threadIdx.x;
    if (i < N_NODES) {
        int off = g_iscan[i] - g_cnt[i] + g_boff[blockIdx.x];
        g_rowoff[i] = off;
        g_cursor[i] = off;
    }
}

__global__ void k_scatter(const void* __restrict__ eiv) {
    int e = blockIdx.x * blockDim.x + threadIdx.x;
    if (e < N_EDGES) {
        int d = load_idx(eiv, N_EDGES + e);
        int s = load_idx(eiv, e);
        if ((unsigned)d < (unsigned)N_NODES) {
            int p = atomicAdd(&g_cursor[d], 1);
            g_sorted_src[p] = ((unsigned)s < (unsigned)N_NODES) ? s : 0;
        }
    }
}

// ---------------- node projections (f32x2 packed, 8 nodes / 64-thread block) ----------------
// sh layout: [k][node] so node-PAIRS are adjacent 8-byte-aligned floats.
__global__ void k_nodeproj(const float* __restrict__ x,
                           const float* __restrict__ W_in, const float* __restrict__ b_in,
                           const float* __restrict__ W_lin, const float* __restrict__ W_src,
                           const float* __restrict__ W_dst) {
    __shared__ float sh[D][8];
    int c = threadIdx.x;
    int n0 = blockIdx.x * 8;

    // stage x transposed: sh[k][r] = x[n0+r][k]
#pragma unroll
    for (int r = 0; r < 8; r++) sh[c][r] = x[(n0 + r) * D + c];
    __syncthreads();

    // h = relu(x @ W_in + b_in), node-pairs packed
    float bi = b_in[c];
    unsigned long long hp[4];
#pragma unroll
    for (int p = 0; p < 4; p++) hp[p] = pack2(bi, bi);
#pragma unroll 8
    for (int k = 0; k < D; k++) {
        float w = W_in[k * D + c];
        unsigned long long ww = pack2(w, w);
#pragma unroll
        for (int p = 0; p < 4; p++) {
            unsigned long long xp = *(const unsigned long long*)&sh[k][2 * p];
            hp[p] = fma2(xp, ww, hp[p]);
        }
    }
    float h[8];
#pragma unroll
    for (int p = 0; p < 4; p++) {
        unpack2(hp[p], h[2 * p], h[2 * p + 1]);
        h[2 * p]     = fmaxf(h[2 * p], 0.0f);
        h[2 * p + 1] = fmaxf(h[2 * p + 1], 0.0f);
    }
    __syncthreads();
#pragma unroll
    for (int r = 0; r < 8; r++) sh[c][r] = h[r];
    __syncthreads();

    // v1 = h@W_lin (x_lin), v2 = h@W_src (a_src), v3 = h@W_dst (a_dst)
    unsigned long long v1[4], v2[4], v3[4];
#pragma unroll
    for (int p = 0; p < 4; p++) { v1[p] = 0ull; v2[p] = 0ull; v3[p] = 0ull; }
#pragma unroll 8
    for (int k = 0; k < D; k++) {
        float w1 = W_lin[k * D + c];
        float w2 = W_src[k * D + c];
        float w3 = W_dst[k * D + c];
        unsigned long long ww1 = pack2(w1, w1);
        unsigned long long ww2 = pack2(w2, w2);
        unsigned long long ww3 = pack2(w3, w3);
#pragma unroll
        for (int p = 0; p < 4; p++) {
            unsigned long long hpair = *(const unsigned long long*)&sh[k][2 * p];
            v1[p] = fma2(hpair, ww1, v1[p]);
            v2[p] = fma2(hpair, ww2, v2[p]);
            v3[p] = fma2(hpair, ww3, v3[p]);
        }
    }
#pragma unroll
    for (int p = 0; p < 4; p++) {
        float xl0, xl1, as0, as1, ad0, ad1;
        unpack2(v1[p], xl0, xl1);
        unpack2(v2[p], as0, as1);
        unpack2(v3[p], ad0, ad1);
        int na = n0 + 2 * p, nb = na + 1;
        g_pack[na * D + c] = make_float2(as0, xl0);
        g_pack[nb * D + c] = make_float2(as1, xl1);
        g_adst[na * D + c] = ad0;
        g_adst[nb * D + c] = ad1;
    }
}

// ---------------- edge pass: segment softmax (no max needed) + aggregate ----------------
// one 64-thread block per dst node; thread = channel. Logits bounded (|a| < ~8) so
// exp without max-subtraction is exact up to fp32 rounding — identical result.
__global__ void k_edge(const float* __restrict__ pos,
                       const float* __restrict__ W_pos, const float* __restrict__ b_pos) {
    __shared__ int sidx[64];
    int dst = blockIdx.x;
    int c = threadIdx.x;

    int rs = g_rowoff[dst];
    int re = g_rowoff[dst + 1];

    float ad  = g_adst[dst * D + c];
    float pd0 = pos[dst * 3 + 0];
    float pd1 = pos[dst * 3 + 1];
    float pd2 = pos[dst * 3 + 2];
    float wp0 = W_pos[0 * D + c];
    float wp1 = W_pos[1 * D + c];
    float wp2 = W_pos[2 * D + c];
    float bp  = b_pos[c];
    float adb = ad + bp;   // fold bias into the dst-side constant

    float s = 0.0f;
    float acc = 0.0f;

    for (int base = rs; base < re; base += 64) {
        int len = min(64, re - base);
        __syncthreads();
        if (c < len) sidx[c] = g_sorted_src[base + c];
        __syncthreads();
#pragma unroll 2
        for (int j = 0; j < len; j++) {
            int src = sidx[j];
            float2 ax = g_pack[src * D + c];
            float p0 = pos[src * 3 + 0];
            float p1 = pos[src * 3 + 1];
            float p2 = pos[src * 3 + 2];
            float delta = fmaf(pd2 - p2, wp2, fmaf(pd1 - p1, wp1, (pd0 - p0) * wp0));
            float a = adb - ax.x + delta;
            float e = __expf(a);
            s += e;
            acc = fmaf(e, ax.y + delta + bp, acc);
        }
    }

    g_agg[dst * D + c] = acc / (s + 1e-16f);
}

// ---------------- out projection: out = relu(agg @ W_out + b_out) ----------------
__global__ void k_outproj(const float* __restrict__ W_out, const float* __restrict__ b_out,
                          float* __restrict__ out) {
    __shared__ float sh[D][8];
    int c = threadIdx.x;
    int n0 = blockIdx.x * 8;

#pragma unroll
    for (int r = 0; r < 8; r++) sh[c][r] = g_agg[(n0 + r) * D + c];
    __syncthreads();

    float bo = b_out[c];
    unsigned long long op[4];
#pragma unroll
    for (int p = 0; p < 4; p++) op[p] = pack2(bo, bo);
#pragma unroll 8
    for (int k = 0; k < D; k++) {
        float w = W_out[k * D + c];
        unsigned long long ww = pack2(w, w);
#pragma unroll
        for (int p = 0; p < 4; p++) {
            unsigned long long ap = *(const unsigned long long*)&sh[k][2 * p];
            op[p] = fma2(ap, ww, op[p]);
        }
    }
#pragma unroll
    for (int p = 0; p < 4; p++) {
        float o0, o1;
        unpack2(op[p], o0, o1);
        out[(n0 + 2 * p) * D + c]     = fmaxf(o0, 0.0f);
        out[(n0 + 2 * p + 1) * D + c] = fmaxf(o1, 0.0f);
    }
}

// ---------------- launch ----------------
extern "C" void kernel_launch(void* const* d_in, const int* in_sizes, int n_in,
                              void* d_out, int out_size) {
    const float* x     = (const float*)d_in[0];
    const float* pos   = (const float*)d_in[1];
    const void*  ei    = d_in[2];
    const float* W_in  = (const float*)d_in[3];
    const float* b_in  = (const float*)d_in[4];
    const float* W_lin = (const float*)d_in[5];
    const float* W_src = (const float*)d_in[6];
    const float* W_dst = (const float*)d_in[7];
    const float* W_pos = (const float*)d_in[8];
    const float* b_pos = (const float*)d_in[9];
    const float* W_out = (const float*)d_in[10];
    const float* b_out = (const float*)d_in[11];
    float* out = (float*)d_out;

    k_detect<<<1, 1>>>(ei);
    k_zero_cnt<<<(N_NODES + 255) / 256, 256>>>();
    k_hist<<<(N_EDGES + 255) / 256, 256>>>(ei);
    k_blockscan<<<NB, 1024>>>();
    k_bsum_scan<<<1, 32>>>();
    k_finalize<<<NB, 1024>>>();
    k_scatter<<<(N_EDGES + 255) / 256, 256>>>(ei);
    k_nodeproj<<<N_NODES / 8, 64>>>(x, W_in, b_in, W_lin, W_src, W_dst);
    k_edge<<<N_NODES, 64>>>(pos, W_pos, b_pos);
    k_outproj<<<N_NODES / 8, 64>>>(W_out, b_out, out);
}

// round 4
// speedup vs baseline: 2.3282x; 1.2624x over previous
#include <cuda_runtime.h>

#define N_NODES 100000
#define N_EDGES 1250000
#define D 64
#define NB 98          // scan blocks: ceil(N/1024)

// ---------------- scratch (static __device__ — allocation-free) ----------------
__device__ int    g_is64;
__device__ int    g_cnt[N_NODES];
__device__ int    g_iscan[N_NODES];
__device__ int    g_rowoff[N_NODES + 1];
__device__ int    g_cursor[N_NODES];
__device__ int    g_bsum[NB];
__device__ int    g_boff[NB];
__device__ int    g_sorted_src[N_EDGES];
__device__ float2 g_pack[N_NODES * D];   // (Q, R) = (exp(-a_src-u), x_lin-u)
__device__ float  g_u[N_NODES * D];      // u = pos @ W_pos
__device__ float  g_agg[N_NODES * D];    // aggregated messages (pre out-proj)

// ---------------- f32x2 packed helpers ----------------
__device__ __forceinline__ unsigned long long pack2(float lo, float hi) {
    unsigned long long r;
    asm("mov.b64 %0, {%1, %2};" : "=l"(r) : "f"(lo), "f"(hi));
    return r;
}
__device__ __forceinline__ void unpack2(unsigned long long v, float& lo, float& hi) {
    asm("mov.b64 {%0, %1}, %2;" : "=f"(lo), "=f"(hi) : "l"(v));
}
__device__ __forceinline__ unsigned long long fma2(unsigned long long a,
                                                   unsigned long long b,
                                                   unsigned long long c) {
    unsigned long long d;
    asm("fma.rn.f32x2 %0, %1, %2, %3;" : "=l"(d) : "l"(a), "l"(b), "l"(c));
    return d;
}

// ---------------- dtype detection for edge_index ----------------
__global__ void k_detect(const void* __restrict__ eiv) {
    const long long* p = (const long long*)eiv;
    int is64 = 1;
    for (int i = 0; i < 16; i++) {
        long long v = p[i];
        if (v < 0 || v >= (long long)N_NODES) is64 = 0;
    }
    g_is64 = is64;
}

__device__ __forceinline__ int load_idx(const void* eiv, int pos64) {
    if (g_is64) return (int)((const long long*)eiv)[pos64];
    return ((const int*)eiv)[pos64];
}

// ---------------- counting sort of edges by dst ----------------
__global__ void k_zero_cnt() {
    int i = blockIdx.x * blockDim.x + threadIdx.x;
    if (i < N_NODES) g_cnt[i] = 0;
}

__global__ void k_hist(const void* __restrict__ eiv) {
    int e = blockIdx.x * blockDim.x + threadIdx.x;
    if (e < N_EDGES) {
        int d = load_idx(eiv, N_EDGES + e);
        if ((unsigned)d < (unsigned)N_NODES) atomicAdd(&g_cnt[d], 1);
    }
}

__global__ void k_blockscan() {
    __shared__ int warpsum[32];
    int t = threadIdx.x;
    int i = blockIdx.x * 1024 + t;
    int v = (i < N_NODES) ? g_cnt[i] : 0;
    int x = v;
#pragma unroll
    for (int o = 1; o < 32; o <<= 1) {
        int y = __shfl_up_sync(0xffffffffu, x, o);
        if ((t & 31) >= o) x += y;
    }
    if ((t & 31) == 31) warpsum[t >> 5] = x;
    __syncthreads();
    if (t < 32) {
        int w = warpsum[t];
#pragma unroll
        for (int o = 1; o < 32; o <<= 1) {
            int y = __shfl_up_sync(0xffffffffu, w, o);
            if (t >= o) w += y;
        }
        warpsum[t] = w;
    }
    __syncthreads();
    int wid = t >> 5;
    int incl = x + (wid ? warpsum[wid - 1] : 0);
    if (i < N_NODES) g_iscan[i] = incl;
    if (t == 1023) g_bsum[blockIdx.x] = incl;
}

__global__ void k_bsum_scan() {
    int t = threadIdx.x;
    int loc[4];
    int s = 0;
#pragma unroll
    for (int j = 0; j < 4; j++) {
        int i = t * 4 + j;
        int v = (i < NB) ? g_bsum[i] : 0;
        loc[j] = s;
        s += v;
    }
    int x = s;
#pragma unroll
    for (int o = 1; o < 32; o <<= 1) {
        int y = __shfl_up_sync(0xffffffffu, x, o);
        if (t >= o) x += y;
    }
    int excl = x - s;
#pragma unroll
    for (int j = 0; j < 4; j++) {
        int i = t * 4 + j;
        if (i < NB) g_boff[i] = excl + loc[j];
    }
    if (t == 31) g_rowoff[N_NODES] = x;
}

__global__ void k_finalize() {
    int i = blockIdx.x * 1024 + threadIdx.x;
    if (i < N_NODES) {
        int off = g_iscan[i] - g_cnt[i] + g_boff[blockIdx.x];
        g_rowoff[i] = off;
        g_cursor[i] = off;
    }
}

__global__ void k_scatter(const void* __restrict__ eiv) {
    int e = blockIdx.x * blockDim.x + threadIdx.x;
    if (e < N_EDGES) {
        int d = load_idx(eiv, N_EDGES + e);
        int s = load_idx(eiv, e);
        if ((unsigned)d < (unsigned)N_NODES) {
            int p = atomicAdd(&g_cursor[d], 1);
            g_sorted_src[p] = ((unsigned)s < (unsigned)N_NODES) ? s : 0;
        }
    }
}

// ---------------- node projections + per-node softmax precompute ----------------
// h = relu(xW_in+b); x_lin = hW_lin; a_src = hW_src; u = pos@W_pos
// Q = exp(-a_src-u), R = x_lin-u  (dst-side terms cancel in segment softmax, so
// W_dst is dead code). 8 nodes per 64-thread block, f32x2 packed.
__global__ void k_nodeproj(const float* __restrict__ x, const float* __restrict__ pos,
                           const float* __restrict__ W_in, const float* __restrict__ b_in,
                           const float* __restrict__ W_lin, const float* __restrict__ W_src,
                           const float* __restrict__ W_pos) {
    __shared__ float sh[D][8];
    __shared__ float spos[24];
    int c = threadIdx.x;
    int n0 = blockIdx.x * 8;

#pragma unroll
    for (int r = 0; r < 8; r++) sh[c][r] = x[(n0 + r) * D + c];
    if (c < 24) spos[c] = pos[n0 * 3 + c];
    __syncthreads();

    // h = relu(x @ W_in + b_in)
    float bi = b_in[c];
    unsigned long long hp[4];
#pragma unroll
    for (int p = 0; p < 4; p++) hp[p] = pack2(bi, bi);
#pragma unroll 8
    for (int k = 0; k < D; k++) {
        float w = W_in[k * D + c];
        unsigned long long ww = pack2(w, w);
#pragma unroll
        for (int p = 0; p < 4; p++) {
            unsigned long long xp = *(const unsigned long long*)&sh[k][2 * p];
            hp[p] = fma2(xp, ww, hp[p]);
        }
    }
    float h[8];
#pragma unroll
    for (int p = 0; p < 4; p++) {
        unpack2(hp[p], h[2 * p], h[2 * p + 1]);
        h[2 * p]     = fmaxf(h[2 * p], 0.0f);
        h[2 * p + 1] = fmaxf(h[2 * p + 1], 0.0f);
    }
    __syncthreads();
#pragma unroll
    for (int r = 0; r < 8; r++) sh[c][r] = h[r];
    __syncthreads();

    // u[r] = pos[r] @ W_pos column c
    float wp0 = W_pos[0 * D + c], wp1 = W_pos[1 * D + c], wp2 = W_pos[2 * D + c];
    float u[8];
#pragma unroll
    for (int r = 0; r < 8; r++)
        u[r] = fmaf(spos[r * 3 + 2], wp2, fmaf(spos[r * 3 + 1], wp1, spos[r * 3 + 0] * wp0));

    // v1 = h@W_lin (x_lin), v2 = h@W_src (a_src)
    unsigned long long v1[4], v2[4];
#pragma unroll
    for (int p = 0; p < 4; p++) { v1[p] = 0ull; v2[p] = 0ull; }
#pragma unroll 8
    for (int k = 0; k < D; k++) {
        float w1 = W_lin[k * D + c];
        float w2 = W_src[k * D + c];
        unsigned long long ww1 = pack2(w1, w1);
        unsigned long long ww2 = pack2(w2, w2);
#pragma unroll
        for (int p = 0; p < 4; p++) {
            unsigned long long hpair = *(const unsigned long long*)&sh[k][2 * p];
            v1[p] = fma2(hpair, ww1, v1[p]);
            v2[p] = fma2(hpair, ww2, v2[p]);
        }
    }
#pragma unroll
    for (int p = 0; p < 4; p++) {
        float xl0, xl1, as0, as1;
        unpack2(v1[p], xl0, xl1);
        unpack2(v2[p], as0, as1);
        int na = n0 + 2 * p, nb = na + 1;
        float u0 = u[2 * p], u1 = u[2 * p + 1];
        g_pack[na * D + c] = make_float2(__expf(-as0 - u0), xl0 - u0);
        g_pack[nb * D + c] = make_float2(__expf(-as1 - u1), xl1 - u1);
        g_u[na * D + c] = u0;
        g_u[nb * D + c] = u1;
    }
}

// ---------------- edge pass: agg = (Σ Q·R)/(Σ Q) + (u[dst]+b_pos) ----------------
// one 64-thread block (2 warps) per dst node; thread = channel; src indices
// broadcast within each warp via shuffle. No exp, no pos math in the loop.
__global__ void k_edge(const float* __restrict__ b_pos) {
    int dst = blockIdx.x;
    int c = threadIdx.x;
    int lane = c & 31;

    int rs = g_rowoff[dst];
    int re = g_rowoff[dst + 1];

    float sq0 = 0.f, sr0 = 0.f, sq1 = 0.f, sr1 = 0.f;

    for (int base = rs; base < re; base += 32) {
        int m = min(32, re - base);
        int idx = (lane < m) ? g_sorted_src[base + lane] : 0;
        int j = 0;
        for (; j + 2 <= m; j += 2) {
            int s0 = __shfl_sync(0xffffffffu, idx, j);
            int s1 = __shfl_sync(0xffffffffu, idx, j + 1);
            float2 qr0 = g_pack[s0 * D + c];
            float2 qr1 = g_pack[s1 * D + c];
            sq0 += qr0.x;
            sr0 = fmaf(qr0.x, qr0.y, sr0);
            sq1 += qr1.x;
            sr1 = fmaf(qr1.x, qr1.y, sr1);
        }
        if (j < m) {
            int s0 = __shfl_sync(0xffffffffu, idx, j);
            float2 qr0 = g_pack[s0 * D + c];
            sq0 += qr0.x;
            sr0 = fmaf(qr0.x, qr0.y, sr0);
        }
    }

    float sq = sq0 + sq1;
    float sr = sr0 + sr1;
    float K = g_u[dst * D + c] + b_pos[c];
    g_agg[dst * D + c] = (re > rs) ? (sr / sq + K) : 0.0f;
}

// ---------------- out projection: out = relu(agg @ W_out + b_out) ----------------
__global__ void k_outproj(const float* __restrict__ W_out, const float* __restrict__ b_out,
                          float* __restrict__ out) {
    __shared__ float sh[D][8];
    int c = threadIdx.x;
    int n0 = blockIdx.x * 8;

#pragma unroll
    for (int r = 0; r < 8; r++) sh[c][r] = g_agg[(n0 + r) * D + c];
    __syncthreads();

    float bo = b_out[c];
    unsigned long long op[4];
#pragma unroll
    for (int p = 0; p < 4; p++) op[p] = pack2(bo, bo);
#pragma unroll 8
    for (int k = 0; k < D; k++) {
        float w = W_out[k * D + c];
        unsigned long long ww = pack2(w, w);
#pragma unroll
        for (int p = 0; p < 4; p++) {
            unsigned long long ap = *(const unsigned long long*)&sh[k][2 * p];
            op[p] = fma2(ap, ww, op[p]);
        }
    }
#pragma unroll
    for (int p = 0; p < 4; p++) {
        float o0, o1;
        unpack2(op[p], o0, o1);
        out[(n0 + 2 * p) * D + c]     = fmaxf(o0, 0.0f);
        out[(n0 + 2 * p + 1) * D + c] = fmaxf(o1, 0.0f);
    }
}

// ---------------- launch ----------------
extern "C" void kernel_launch(void* const* d_in, const int* in_sizes, int n_in,
                              void* d_out, int out_size) {
    const float* x     = (const float*)d_in[0];
    const float* pos   = (const float*)d_in[1];
    const void*  ei    = d_in[2];
    const float* W_in  = (const float*)d_in[3];
    const float* b_in  = (const float*)d_in[4];
    const float* W_lin = (const float*)d_in[5];
    const float* W_src = (const float*)d_in[6];
    // d_in[7] = W_dst: provably dead (dst-side softmax terms cancel)
    const float* W_pos = (const float*)d_in[8];
    const float* b_pos = (const float*)d_in[9];
    const float* W_out = (const float*)d_in[10];
    const float* b_out = (const float*)d_in[11];
    float* out = (float*)d_out;

    k_detect<<<1, 1>>>(ei);
    k_zero_cnt<<<(N_NODES + 255) / 256, 256>>>();
    k_hist<<<(N_EDGES + 255) / 256, 256>>>(ei);
    k_blockscan<<<NB, 1024>>>();
    k_bsum_scan<<<1, 32>>>();
    k_finalize<<<NB, 1024>>>();
    k_scatter<<<(N_EDGES + 255) / 256, 256>>>(ei);
    k_nodeproj<<<N_NODES / 8, 64>>>(x, pos, W_in, b_in, W_lin, W_src, W_pos);
    k_edge<<<N_NODES, 64>>>(b_pos);
    k_outproj<<<N_NODES / 8, 64>>>(W_out, b_out, out);
}

// round 5
// speedup vs baseline: 2.7299x; 1.1725x over previous
#include <cuda_runtime.h>
#include <cuda_fp16.h>

#define N_NODES 100000
#define N_EDGES 1250000
#define D 64
#define NB 98          // scan blocks: ceil(N/1024)

// ---------------- scratch (static __device__ — allocation-free) ----------------
__device__ int     g_is64;
__device__ int     g_cnt[N_NODES];
__device__ int     g_iscan[N_NODES];
__device__ int     g_rowoff[N_NODES + 1];
__device__ int     g_cursor[N_NODES];
__device__ int     g_bsum[NB];
__device__ int     g_boff[NB];
__device__ int     g_sorted_src[N_EDGES];
__device__ __half2 g_packh[N_NODES * D];  // per (node,ch): half2(Q, R), Q=exp(-a_src-u), R=x_lin-u
__device__ float   g_u[N_NODES * D];      // u = pos @ W_pos
__device__ float   g_agg[N_NODES * D];    // aggregated messages (pre out-proj)

// ---------------- f32x2 packed helpers ----------------
__device__ __forceinline__ unsigned long long pack2(float lo, float hi) {
    unsigned long long r;
    asm("mov.b64 %0, {%1, %2};" : "=l"(r) : "f"(lo), "f"(hi));
    return r;
}
__device__ __forceinline__ void unpack2(unsigned long long v, float& lo, float& hi) {
    asm("mov.b64 {%0, %1}, %2;" : "=f"(lo), "=f"(hi) : "l"(v));
}
__device__ __forceinline__ unsigned long long fma2(unsigned long long a,
                                                   unsigned long long b,
                                                   unsigned long long c) {
    unsigned long long d;
    asm("fma.rn.f32x2 %0, %1, %2, %3;" : "=l"(d) : "l"(a), "l"(b), "l"(c));
    return d;
}

__device__ __forceinline__ int load_idx(const void* eiv, int pos64) {
    if (g_is64) return (int)((const long long*)eiv)[pos64];
    return ((const int*)eiv)[pos64];
}

// ---------------- zero + edge-index dtype detection (fused) ----------------
__global__ void k_zero_cnt(const void* __restrict__ eiv) {
    int i = blockIdx.x * blockDim.x + threadIdx.x;
    if (i < N_NODES) g_cnt[i] = 0;
    if (i == 0) {
        const long long* p = (const long long*)eiv;
        int is64 = 1;
        for (int j = 0; j < 16; j++) {
            long long v = p[j];
            if (v < 0 || v >= (long long)N_NODES) is64 = 0;
        }
        g_is64 = is64;
    }
}

__global__ void k_hist(const void* __restrict__ eiv) {
    int e = blockIdx.x * blockDim.x + threadIdx.x;
    if (e < N_EDGES) {
        int d = load_idx(eiv, N_EDGES + e);
        if ((unsigned)d < (unsigned)N_NODES) atomicAdd(&g_cnt[d], 1);
    }
}

__global__ void k_blockscan() {
    __shared__ int warpsum[32];
    int t = threadIdx.x;
    int i = blockIdx.x * 1024 + t;
    int v = (i < N_NODES) ? g_cnt[i] : 0;
    int x = v;
#pragma unroll
    for (int o = 1; o < 32; o <<= 1) {
        int y = __shfl_up_sync(0xffffffffu, x, o);
        if ((t & 31) >= o) x += y;
    }
    if ((t & 31) == 31) warpsum[t >> 5] = x;
    __syncthreads();
    if (t < 32) {
        int w = warpsum[t];
#pragma unroll
        for (int o = 1; o < 32; o <<= 1) {
            int y = __shfl_up_sync(0xffffffffu, w, o);
            if (t >= o) w += y;
        }
        warpsum[t] = w;
    }
    __syncthreads();
    int wid = t >> 5;
    int incl = x + (wid ? warpsum[wid - 1] : 0);
    if (i < N_NODES) g_iscan[i] = incl;
    if (t == 1023) g_bsum[blockIdx.x] = incl;
}

__global__ void k_bsum_scan() {
    int t = threadIdx.x;
    int loc[4];
    int s = 0;
#pragma unroll
    for (int j = 0; j < 4; j++) {
        int i = t * 4 + j;
        int v = (i < NB) ? g_bsum[i] : 0;
        loc[j] = s;
        s += v;
    }
    int x = s;
#pragma unroll
    for (int o = 1; o < 32; o <<= 1) {
        int y = __shfl_up_sync(0xffffffffu, x, o);
        if (t >= o) x += y;
    }
    int excl = x - s;
#pragma unroll
    for (int j = 0; j < 4; j++) {
        int i = t * 4 + j;
        if (i < NB) g_boff[i] = excl + loc[j];
    }
    if (t == 31) g_rowoff[N_NODES] = x;
}

__global__ void k_finalize() {
    int i = blockIdx.x * 1024 + threadIdx.x;
    if (i < N_NODES) {
        int off = g_iscan[i] - g_cnt[i] + g_boff[blockIdx.x];
        g_rowoff[i] = off;
        g_cursor[i] = off;
    }
}

__global__ void k_scatter(const void* __restrict__ eiv) {
    int e = blockIdx.x * blockDim.x + threadIdx.x;
    if (e < N_EDGES) {
        int d = load_idx(eiv, N_EDGES + e);
        int s = load_idx(eiv, e);
        if ((unsigned)d < (unsigned)N_NODES) {
            int p = atomicAdd(&g_cursor[d], 1);
            g_sorted_src[p] = ((unsigned)s < (unsigned)N_NODES) ? s : 0;
        }
    }
}

// ---------------- node projections + per-node softmax precompute ----------------
// h = relu(xW_in+b); Q = exp(-(h@W_src)-u), R = (h@W_lin)-u, u = pos@W_pos.
// (dst-side softmax terms cancel; W_dst is dead.) 8 nodes / 64-thread block, f32x2.
__global__ void k_nodeproj(const float* __restrict__ x, const float* __restrict__ pos,
                           const float* __restrict__ W_in, const float* __restrict__ b_in,
                           const float* __restrict__ W_lin, const float* __restrict__ W_src,
                           const float* __restrict__ W_pos) {
    __shared__ float sh[D][8];
    __shared__ float spos[24];
    int c = threadIdx.x;
    int n0 = blockIdx.x * 8;

#pragma unroll
    for (int r = 0; r < 8; r++) sh[c][r] = x[(n0 + r) * D + c];
    if (c < 24) spos[c] = pos[n0 * 3 + c];
    __syncthreads();

    float bi = b_in[c];
    unsigned long long hp[4];
#pragma unroll
    for (int p = 0; p < 4; p++) hp[p] = pack2(bi, bi);
#pragma unroll 8
    for (int k = 0; k < D; k++) {
        float w = W_in[k * D + c];
        unsigned long long ww = pack2(w, w);
#pragma unroll
        for (int p = 0; p < 4; p++) {
            unsigned long long xp = *(const unsigned long long*)&sh[k][2 * p];
            hp[p] = fma2(xp, ww, hp[p]);
        }
    }
    float h[8];
#pragma unroll
    for (int p = 0; p < 4; p++) {
        unpack2(hp[p], h[2 * p], h[2 * p + 1]);
        h[2 * p]     = fmaxf(h[2 * p], 0.0f);
        h[2 * p + 1] = fmaxf(h[2 * p + 1], 0.0f);
    }
    __syncthreads();
#pragma unroll
    for (int r = 0; r < 8; r++) sh[c][r] = h[r];
    __syncthreads();

    float wp0 = W_pos[0 * D + c], wp1 = W_pos[1 * D + c], wp2 = W_pos[2 * D + c];
    float u[8];
#pragma unroll
    for (int r = 0; r < 8; r++)
        u[r] = fmaf(spos[r * 3 + 2], wp2, fmaf(spos[r * 3 + 1], wp1, spos[r * 3 + 0] * wp0));

    unsigned long long v1[4], v2[4];
#pragma unroll
    for (int p = 0; p < 4; p++) { v1[p] = 0ull; v2[p] = 0ull; }
#pragma unroll 8
    for (int k = 0; k < D; k++) {
        float w1 = W_lin[k * D + c];
        float w2 = W_src[k * D + c];
        unsigned long long ww1 = pack2(w1, w1);
        unsigned long long ww2 = pack2(w2, w2);
#pragma unroll
        for (int p = 0; p < 4; p++) {
            unsigned long long hpair = *(const unsigned long long*)&sh[k][2 * p];
            v1[p] = fma2(hpair, ww1, v1[p]);
            v2[p] = fma2(hpair, ww2, v2[p]);
        }
    }
#pragma unroll
    for (int p = 0; p < 4; p++) {
        float xl0, xl1, as0, as1;
        unpack2(v1[p], xl0, xl1);
        unpack2(v2[p], as0, as1);
        int na = n0 + 2 * p, nb = na + 1;
        float u0 = u[2 * p], u1 = u[2 * p + 1];
        g_packh[na * D + c] = __floats2half2_rn(__expf(-as0 - u0), xl0 - u0);
        g_packh[nb * D + c] = __floats2half2_rn(__expf(-as1 - u1), xl1 - u1);
        g_u[na * D + c] = u0;
        g_u[nb * D + c] = u1;
    }
}

// ---------------- edge pass: agg = (Σ Q·R)/(Σ Q) + (u[dst]+b_pos) ----------------
// warp per dst node; lane owns channels {2*lane, 2*lane+1}; one 8-B load per
// edge per lane = one coalesced 256-B warp transaction per edge.
__global__ void k_edge(const float* __restrict__ b_pos) {
    int warp = threadIdx.x >> 5;
    int lane = threadIdx.x & 31;
    int dst = blockIdx.x * 4 + warp;
    if (dst >= N_NODES) return;

    int rs = g_rowoff[dst];
    int re = g_rowoff[dst + 1];

    float sq0 = 0.f, sr0 = 0.f, sq1 = 0.f, sr1 = 0.f;

    for (int base = rs; base < re; base += 32) {
        int m = min(32, re - base);
        int idx = (lane < m) ? g_sorted_src[base + lane] : 0;
        int j = 0;
        for (; j + 2 <= m; j += 2) {
            int s0 = __shfl_sync(0xffffffffu, idx, j);
            int s1 = __shfl_sync(0xffffffffu, idx, j + 1);
            uint2 v0 = *reinterpret_cast<const uint2*>(&g_packh[s0 * D + 2 * lane]);
            uint2 v1 = *reinterpret_cast<const uint2*>(&g_packh[s1 * D + 2 * lane]);
            float2 a0 = __half22float2(*reinterpret_cast<const __half2*>(&v0.x));
            float2 b0 = __half22float2(*reinterpret_cast<const __half2*>(&v0.y));
            float2 a1 = __half22float2(*reinterpret_cast<const __half2*>(&v1.x));
            float2 b1 = __half22float2(*reinterpret_cast<const __half2*>(&v1.y));
            sq0 += a0.x; sr0 = fmaf(a0.x, a0.y, sr0);
            sq1 += b0.x; sr1 = fmaf(b0.x, b0.y, sr1);
            sq0 += a1.x; sr0 = fmaf(a1.x, a1.y, sr0);
            sq1 += b1.x; sr1 = fmaf(b1.x, b1.y, sr1);
        }
        if (j < m) {
            int s0 = __shfl_sync(0xffffffffu, idx, j);
            uint2 v0 = *reinterpret_cast<const uint2*>(&g_packh[s0 * D + 2 * lane]);
            float2 a0 = __half22float2(*reinterpret_cast<const __half2*>(&v0.x));
            float2 b0 = __half22float2(*reinterpret_cast<const __half2*>(&v0.y));
            sq0 += a0.x; sr0 = fmaf(a0.x, a0.y, sr0);
            sq1 += b0.x; sr1 = fmaf(b0.x, b0.y, sr1);
        }
    }

    int c0 = 2 * lane;
    if (re > rs) {
        g_agg[dst * D + c0]     = sr0 / sq0 + g_u[dst * D + c0]     + b_pos[c0];
        g_agg[dst * D + c0 + 1] = sr1 / sq1 + g_u[dst * D + c0 + 1] + b_pos[c0 + 1];
    } else {
        g_agg[dst * D + c0]     = 0.0f;
        g_agg[dst * D + c0 + 1] = 0.0f;
    }
}

// ---------------- out projection: out = relu(agg @ W_out + b_out) ----------------
__global__ void k_outproj(const float* __restrict__ W_out, const float* __restrict__ b_out,
                          float* __restrict__ out) {
    __shared__ float sh[D][8];
    int c = threadIdx.x;
    int n0 = blockIdx.x * 8;

#pragma unroll
    for (int r = 0; r < 8; r++) sh[c][r] = g_agg[(n0 + r) * D + c];
    __syncthreads();

    float bo = b_out[c];
    unsigned long long op[4];
#pragma unroll
    for (int p = 0; p < 4; p++) op[p] = pack2(bo, bo);
#pragma unroll 8
    for (int k = 0; k < D; k++) {
        float w = W_out[k * D + c];
        unsigned long long ww = pack2(w, w);
#pragma unroll
        for (int p = 0; p < 4; p++) {
            unsigned long long ap = *(const unsigned long long*)&sh[k][2 * p];
            op[p] = fma2(ap, ww, op[p]);
        }
    }
#pragma unroll
    for (int p = 0; p < 4; p++) {
        float o0, o1;
        unpack2(op[p], o0, o1);
        out[(n0 + 2 * p) * D + c]     = fmaxf(o0, 0.0f);
        out[(n0 + 2 * p + 1) * D + c] = fmaxf(o1, 0.0f);
    }
}

// ---------------- launch ----------------
extern "C" void kernel_launch(void* const* d_in, const int* in_sizes, int n_in,
                              void* d_out, int out_size) {
    const float* x     = (const float*)d_in[0];
    const float* pos   = (const float*)d_in[1];
    const void*  ei    = d_in[2];
    const float* W_in  = (const float*)d_in[3];
    const float* b_in  = (const float*)d_in[4];
    const float* W_lin = (const float*)d_in[5];
    const float* W_src = (const float*)d_in[6];
    // d_in[7] = W_dst: dead (dst-side softmax terms cancel)
    const float* W_pos = (const float*)d_in[8];
    const float* b_pos = (const float*)d_in[9];
    const float* W_out = (const float*)d_in[10];
    const float* b_out = (const float*)d_in[11];
    float* out = (float*)d_out;

    k_zero_cnt<<<(N_NODES + 255) / 256, 256>>>(ei);
    k_hist<<<(N_EDGES + 255) / 256, 256>>>(ei);
    k_blockscan<<<NB, 1024>>>();
    k_bsum_scan<<<1, 32>>>();
    k_finalize<<<NB, 1024>>>();
    k_scatter<<<(N_EDGES + 255) / 256, 256>>>(ei);
    k_nodeproj<<<N_NODES / 8, 64>>>(x, pos, W_in, b_in, W_lin, W_src, W_pos);
    k_edge<<<(N_NODES + 3) / 4, 128>>>(b_pos);
    k_outproj<<<N_NODES / 8, 64>>>(W_out, b_out, out);
}